// round 2
// baseline (speedup 1.0000x reference)
#include <cuda_runtime.h>
#include <cstdint>
#include <cstdio>

// ---------------------------------------------------------------------------
// Problem constants (fixed by the reference: B=2, frames=16, 32x32 spatial,
// hidden=1024, 16 heads, head_dim=64)
// ---------------------------------------------------------------------------
#define HIDDEN   1024
#define FRAMES   16
#define SPATIAL  1024          // 32*32
#define BATCH    2
#define NSEQ     (BATCH*SPATIAL)        // 2048 temporal sequences
#define TOKENS   (BATCH*FRAMES*SPATIAL) // 32768 tokens
#define NH       16
#define HD       64
#define QKV_N    (3*HIDDEN)             // 3072

// ---------------------------------------------------------------------------
// Scratch (no cudaMalloc allowed) — static device globals
// ---------------------------------------------------------------------------
__device__ float g_xt  [(size_t)TOKENS * HIDDEN];   // LN'd, temporally transposed (128 MB)
__device__ float g_qkv [(size_t)TOKENS * QKV_N];    // QKV activations (384 MB)
__device__ float g_attn[(size_t)TOKENS * HIDDEN];   // attention output, final token order (128 MB)

// ---------------------------------------------------------------------------
// Kernel 1: LayerNorm + transpose into (b*spatial + s, frame, hidden) layout
// one block per token, 256 threads, one float4 per thread
// ---------------------------------------------------------------------------
__global__ __launch_bounds__(256) void ln_transpose_kernel(
    const float* __restrict__ x,
    const float* __restrict__ gamma,
    const float* __restrict__ beta)
{
    const int token = blockIdx.x;         // 0..32767  (= b*16384 + t*1024 + s)
    const int b  = token >> 14;
    const int sg = token & 16383;
    const int t  = sg >> 10;
    const int s  = sg & 1023;

    const int tid = threadIdx.x;          // 256 threads, HIDDEN/4 = 256 float4
    const float4 v = ((const float4*)(x + (size_t)token * HIDDEN))[tid];

    float sum = v.x + v.y + v.z + v.w;
    float sq  = v.x*v.x + v.y*v.y + v.z*v.z + v.w*v.w;

    // warp reduce then block reduce (8 warps)
    #pragma unroll
    for (int o = 16; o > 0; o >>= 1) {
        sum += __shfl_xor_sync(0xffffffffu, sum, o);
        sq  += __shfl_xor_sync(0xffffffffu, sq,  o);
    }
    __shared__ float s_sum[8], s_sq[8];
    __shared__ float s_mu, s_rstd;
    if ((tid & 31) == 0) { s_sum[tid >> 5] = sum; s_sq[tid >> 5] = sq; }
    __syncthreads();
    if (tid == 0) {
        float ts = 0.f, tq = 0.f;
        #pragma unroll
        for (int i = 0; i < 8; ++i) { ts += s_sum[i]; tq += s_sq[i]; }
        const float mu  = ts * (1.0f / HIDDEN);
        const float var = tq * (1.0f / HIDDEN) - mu * mu;
        s_mu = mu;
        s_rstd = rsqrtf(var + 1e-5f);
    }
    __syncthreads();
    const float mu = s_mu, rs = s_rstd;

    const float4 g  = ((const float4*)gamma)[tid];
    const float4 be = ((const float4*)beta)[tid];
    float4 o;
    o.x = (v.x - mu) * rs * g.x + be.x;
    o.y = (v.y - mu) * rs * g.y + be.y;
    o.z = (v.z - mu) * rs * g.z + be.z;
    o.w = (v.w - mu) * rs * g.w + be.w;

    const size_t orow = (size_t)(b * SPATIAL + s) * FRAMES + t;   // n*16 + t
    ((float4*)(g_xt + orow * HIDDEN))[tid] = o;
}

// ---------------------------------------------------------------------------
// Kernel 2/4: classic register-tiled SGEMM, C[M,N] = A[M,K] * B[N,K]^T
// A,B,C row-major; M%128==0, N%128==0, K%16==0 (holds for all our shapes).
// BM=BN=128, BK=16, 256 threads, 8x8 per thread.
// ---------------------------------------------------------------------------
__global__ __launch_bounds__(256) void sgemm_nt(
    const float* __restrict__ A,
    const float* __restrict__ B,
    float*       __restrict__ C,
    int M, int N, int K)
{
    constexpr int BM = 128, BN = 128, BK = 16, TM = 8, TN = 8;
    __shared__ float As[BK][BM];
    __shared__ float Bs[BK][BN];

    const int tid = threadIdx.x;
    const int bm = blockIdx.y * BM;
    const int bn = blockIdx.x * BN;
    const int ty = tid >> 4;     // 0..15
    const int tx = tid & 15;     // 0..15

    const float* Ag = A + (size_t)bm * K;
    const float* Bg = B + (size_t)bn * K;

    float acc[TM][TN];
    #pragma unroll
    for (int i = 0; i < TM; ++i)
        #pragma unroll
        for (int j = 0; j < TN; ++j) acc[i][j] = 0.f;

    for (int k0 = 0; k0 < K; k0 += BK) {
        // stage A,B tiles: 128 rows x 16 cols each = 512 float4, 2 per thread
        #pragma unroll
        for (int i = 0; i < 2; ++i) {
            const int id = tid + i * 256;       // 0..511
            const int r  = id >> 2;             // row within tile
            const int c4 = id & 3;              // which float4 in the row
            const float4 va = *(const float4*)(Ag + (size_t)r * K + k0 + c4 * 4);
            As[c4*4+0][r] = va.x; As[c4*4+1][r] = va.y;
            As[c4*4+2][r] = va.z; As[c4*4+3][r] = va.w;
            const float4 vb = *(const float4*)(Bg + (size_t)r * K + k0 + c4 * 4);
            Bs[c4*4+0][r] = vb.x; Bs[c4*4+1][r] = vb.y;
            Bs[c4*4+2][r] = vb.z; Bs[c4*4+3][r] = vb.w;
        }
        __syncthreads();

        #pragma unroll
        for (int kk = 0; kk < BK; ++kk) {
            float a[TM], bv[TN];
            #pragma unroll
            for (int i = 0; i < TM; ++i) a[i]  = As[kk][ty * TM + i];
            #pragma unroll
            for (int j = 0; j < TN; ++j) bv[j] = Bs[kk][tx * TN + j];
            #pragma unroll
            for (int i = 0; i < TM; ++i)
                #pragma unroll
                for (int j = 0; j < TN; ++j)
                    acc[i][j] += a[i] * bv[j];
        }
        __syncthreads();
    }

    #pragma unroll
    for (int i = 0; i < TM; ++i) {
        float4* crow = (float4*)(C + (size_t)(bm + ty * TM + i) * N + bn + tx * TN);
        crow[0] = make_float4(acc[i][0], acc[i][1], acc[i][2], acc[i][3]);
        crow[1] = make_float4(acc[i][4], acc[i][5], acc[i][6], acc[i][7]);
    }
}

// ---------------------------------------------------------------------------
// Kernel 3: RoPE + causal attention over frames (16x16 per (n,h)).
// One block of 64 threads per (n, h). Writes directly into final token order.
// ---------------------------------------------------------------------------
__global__ __launch_bounds__(64) void attn_kernel()
{
    const int nb = blockIdx.x;       // 0 .. NSEQ*NH-1
    const int n  = nb >> 4;
    const int h  = nb & 15;
    const int tid = threadIdx.x;     // 64 threads

    __shared__ float qs[FRAMES][HD + 1];
    __shared__ float ks[FRAMES][HD + 1];
    __shared__ float vs[FRAMES][HD + 1];
    __shared__ float P [FRAMES][FRAMES + 1];

    const float* base = g_qkv + (size_t)n * FRAMES * QKV_N;

    // load q/k/v tiles for this head
    for (int idx = tid; idx < FRAMES * HD; idx += 64) {
        const int t = idx >> 6;
        const int d = idx & 63;
        const size_t r = (size_t)t * QKV_N + h * HD + d;
        qs[t][d] = base[r];
        ks[t][d] = base[r + HIDDEN];
        vs[t][d] = base[r + 2 * HIDDEN];
    }
    __syncthreads();

    // RoPE (rotate-half convention): angle(t,d) = t * 10000^(-2d/64), d in [0,32)
    for (int idx = tid; idx < FRAMES * 32; idx += 64) {
        const int t = idx >> 5;
        const int d = idx & 31;
        const float inv = __expf(-(float)d * 0.28782313662425576f); // ln(1e4)/32
        float sn, cs;
        __sincosf((float)t * inv, &sn, &cs);
        const float q1 = qs[t][d], q2 = qs[t][d + 32];
        qs[t][d]      = q1 * cs - q2 * sn;
        qs[t][d + 32] = q2 * cs + q1 * sn;
        const float k1 = ks[t][d], k2 = ks[t][d + 32];
        ks[t][d]      = k1 * cs - k2 * sn;
        ks[t][d + 32] = k2 * cs + k1 * sn;
    }
    __syncthreads();

    // scores (causal): 256 entries, 4 per thread
    for (int idx = tid; idx < FRAMES * FRAMES; idx += 64) {
        const int i = idx >> 4;
        const int j = idx & 15;
        float v = -INFINITY;
        if (j <= i) {
            float acc = 0.f;
            #pragma unroll
            for (int d = 0; d < HD; ++d) acc += qs[i][d] * ks[j][d];
            v = acc * 0.125f;            // 1/sqrt(64)
        }
        P[i][j] = v;
    }
    __syncthreads();

    // softmax, one row per thread (16 threads active)
    if (tid < FRAMES) {
        const int i = tid;
        float m = -INFINITY;
        for (int j = 0; j <= i; ++j) m = fmaxf(m, P[i][j]);
        float sum = 0.f;
        for (int j = 0; j <= i; ++j) { const float e = expf(P[i][j] - m); P[i][j] = e; sum += e; }
        const float r = 1.f / sum;
        for (int j = 0; j <= i; ++j) P[i][j] *= r;
        for (int j = i + 1; j < FRAMES; ++j) P[i][j] = 0.f;
    }
    __syncthreads();

    // out[i][d] = sum_j P[i][j] * v[j][d]; write in final (b, t*spatial+s, h*64+d) order
    const int d = tid;                   // 0..63
    const int b = n >> 10;
    const int s = n & 1023;
    #pragma unroll
    for (int i = 0; i < FRAMES; ++i) {
        float acc = 0.f;
        #pragma unroll
        for (int j = 0; j < FRAMES; ++j) acc += P[i][j] * vs[j][d];
        g_attn[(size_t)(b * 16384 + i * 1024 + s) * HIDDEN + h * HD + d] = acc;
    }
}

// ---------------------------------------------------------------------------
// Launch: LN -> QKV GEMM -> attention -> output GEMM
// ---------------------------------------------------------------------------
extern "C" void kernel_launch(void* const* d_in, const int* in_sizes, int n_in,
                              void* d_out, int out_size)
{
    const float* x      = (const float*)d_in[0];
    const float* w_qkv  = (const float*)d_in[1];
    const float* w_out  = (const float*)d_in[2];
    const float* gamma  = (const float*)d_in[3];
    const float* beta   = (const float*)d_in[4];
    float* out = (float*)d_out;

    float *xt, *qkv, *attn;
    cudaGetSymbolAddress((void**)&xt,   g_xt);
    cudaGetSymbolAddress((void**)&qkv,  g_qkv);
    cudaGetSymbolAddress((void**)&attn, g_attn);

    // 1. LayerNorm + temporal transpose
    ln_transpose_kernel<<<TOKENS, 256>>>(x, gamma, beta);

    // 2. QKV projection: [32768,1024] x [3072,1024]^T
    {
        dim3 grid(QKV_N / 128, TOKENS / 128);
        sgemm_nt<<<grid, 256>>>(xt, w_qkv, qkv, TOKENS, QKV_N, HIDDEN);
    }

    // 3. RoPE + causal attention (frames dim), writes final token order
    attn_kernel<<<NSEQ * NH, 64>>>();

    // 4. Output projection: [32768,1024] x [1024,1024]^T -> d_out
    {
        dim3 grid(HIDDEN / 128, TOKENS / 128);
        sgemm_nt<<<grid, 256>>>(attn, w_out, out, TOKENS, HIDDEN, HIDDEN);
    }
}

// round 3
// speedup vs baseline: 1.2608x; 1.2608x over previous
#include <cuda_runtime.h>
#include <cstdint>
#include <cstdio>

// ---------------------------------------------------------------------------
// Problem constants (B=2, frames=16, 32x32 spatial, hidden=1024, 16 heads)
// ---------------------------------------------------------------------------
#define HIDDEN   1024
#define FRAMES   16
#define SPATIAL  1024
#define BATCH    2
#define NSEQ     (BATCH*SPATIAL)        // 2048 temporal sequences
#define TOKENS   (BATCH*FRAMES*SPATIAL) // 32768 tokens
#define NH       16
#define HD       64
#define QKV_N    (3*HIDDEN)             // 3072

// ---------------------------------------------------------------------------
// Scratch
// ---------------------------------------------------------------------------
__device__ float g_xt  [(size_t)TOKENS * HIDDEN];
__device__ float g_qkv [(size_t)TOKENS * QKV_N];
__device__ float g_attn[(size_t)TOKENS * HIDDEN];

// ---------------------------------------------------------------------------
// Kernel 1: LayerNorm + temporal transpose
// ---------------------------------------------------------------------------
__global__ __launch_bounds__(256) void ln_transpose_kernel(
    const float* __restrict__ x,
    const float* __restrict__ gamma,
    const float* __restrict__ beta)
{
    const int token = blockIdx.x;
    const int b  = token >> 14;
    const int sg = token & 16383;
    const int t  = sg >> 10;
    const int s  = sg & 1023;

    const int tid = threadIdx.x;
    const float4 v = ((const float4*)(x + (size_t)token * HIDDEN))[tid];

    float sum = v.x + v.y + v.z + v.w;
    float sq  = v.x*v.x + v.y*v.y + v.z*v.z + v.w*v.w;

    #pragma unroll
    for (int o = 16; o > 0; o >>= 1) {
        sum += __shfl_xor_sync(0xffffffffu, sum, o);
        sq  += __shfl_xor_sync(0xffffffffu, sq,  o);
    }
    __shared__ float s_sum[8], s_sq[8];
    __shared__ float s_mu, s_rstd;
    if ((tid & 31) == 0) { s_sum[tid >> 5] = sum; s_sq[tid >> 5] = sq; }
    __syncthreads();
    if (tid == 0) {
        float ts = 0.f, tq = 0.f;
        #pragma unroll
        for (int i = 0; i < 8; ++i) { ts += s_sum[i]; tq += s_sq[i]; }
        const float mu  = ts * (1.0f / HIDDEN);
        const float var = tq * (1.0f / HIDDEN) - mu * mu;
        s_mu = mu;
        s_rstd = rsqrtf(var + 1e-5f);
    }
    __syncthreads();
    const float mu = s_mu, rs = s_rstd;

    const float4 g  = ((const float4*)gamma)[tid];
    const float4 be = ((const float4*)beta)[tid];
    float4 o;
    o.x = (v.x - mu) * rs * g.x + be.x;
    o.y = (v.y - mu) * rs * g.y + be.y;
    o.z = (v.z - mu) * rs * g.z + be.z;
    o.w = (v.w - mu) * rs * g.w + be.w;

    const size_t orow = (size_t)(b * SPATIAL + s) * FRAMES + t;
    ((float4*)(g_xt + orow * HIDDEN))[tid] = o;
}

// ---------------------------------------------------------------------------
// TF32x3 tensor-core GEMM: C[M,N] = A[M,K] * B[N,K]^T  (all row-major)
// BM=BN=128, BK=16, 256 threads (8 warps, 2x4), warp tile 64x32.
// smem [row][k] with 16B-granular XOR swizzle; hi/lo split at frag load.
// ---------------------------------------------------------------------------
__device__ __forceinline__ void tf32_split(float a, uint32_t& hi, uint32_t& lo) {
    uint32_t h;
    asm("cvt.rna.tf32.f32 %0, %1;" : "=r"(h) : "f"(a));
    float r = a - __uint_as_float(h);
    asm("cvt.rna.tf32.f32 %0, %1;" : "=r"(lo) : "f"(r));
    hi = h;
}

__device__ __forceinline__ void mma_tf32(float* d, const uint32_t* a, const uint32_t* b) {
    asm volatile("mma.sync.aligned.m16n8k8.row.col.f32.tf32.tf32.f32 "
        "{%0,%1,%2,%3}, {%4,%5,%6,%7}, {%8,%9}, {%0,%1,%2,%3};"
        : "+f"(d[0]), "+f"(d[1]), "+f"(d[2]), "+f"(d[3])
        : "r"(a[0]), "r"(a[1]), "r"(a[2]), "r"(a[3]), "r"(b[0]), "r"(b[1]));
}

// swizzled index inside a 128x16 tile: element (r,k) -> r*16 + (k ^ (4*((r>>1)&3)))
__device__ __forceinline__ int swidx(int r, int k) {
    return (r << 4) + (k ^ ((((r >> 1) & 3)) << 2));
}

__global__ __launch_bounds__(256, 2) void sgemm_tf32x3(
    const float* __restrict__ A,
    const float* __restrict__ B,
    float*       __restrict__ C,
    int M, int N, int K)
{
    __shared__ float As[2][128 * 16];
    __shared__ float Bs[2][128 * 16];

    const int tid  = threadIdx.x;
    const int lane = tid & 31;
    const int wid  = tid >> 5;
    const int wm   = wid >> 2;          // 0..1
    const int wn   = wid & 3;           // 0..3
    const int g    = lane >> 2;         // 0..7
    const int cq   = lane & 3;          // 0..3

    const int bm = blockIdx.y * 128;
    const int bn = blockIdx.x * 128;

    float acc[4][4][4];
    #pragma unroll
    for (int i = 0; i < 4; ++i)
        #pragma unroll
        for (int j = 0; j < 4; ++j)
            #pragma unroll
            for (int e = 0; e < 4; ++e) acc[i][j][e] = 0.f;

    // staging coords for this thread: 2 float4 each for A,B per stage
    const int r0s = tid >> 2;           // 0..63   (i=0)
    const int r1s = r0s + 64;           // 64..127 (i=1)
    const int chs = tid & 3;            // 16B chunk within the 64B row

    // --- prologue: stage k0=0 into buf 0 ---
    {
        float4 a0 = *(const float4*)(A + (size_t)(bm + r0s) * K + chs * 4);
        float4 a1 = *(const float4*)(A + (size_t)(bm + r1s) * K + chs * 4);
        float4 b0 = *(const float4*)(B + (size_t)(bn + r0s) * K + chs * 4);
        float4 b1 = *(const float4*)(B + (size_t)(bn + r1s) * K + chs * 4);
        *(float4*)&As[0][swidx(r0s, chs * 4)] = a0;
        *(float4*)&As[0][swidx(r1s, chs * 4)] = a1;
        *(float4*)&Bs[0][swidx(r0s, chs * 4)] = b0;
        *(float4*)&Bs[0][swidx(r1s, chs * 4)] = b1;
    }
    __syncthreads();

    int buf = 0;
    for (int k0 = 0; k0 < K; k0 += 16) {
        const bool has_next = (k0 + 16) < K;
        float4 pa0, pa1, pb0, pb1;
        if (has_next) {
            const int kn = k0 + 16;
            pa0 = *(const float4*)(A + (size_t)(bm + r0s) * K + kn + chs * 4);
            pa1 = *(const float4*)(A + (size_t)(bm + r1s) * K + kn + chs * 4);
            pb0 = *(const float4*)(B + (size_t)(bn + r0s) * K + kn + chs * 4);
            pb1 = *(const float4*)(B + (size_t)(bn + r1s) * K + kn + chs * 4);
        }

        const float* as = As[buf];
        const float* bs = Bs[buf];

        #pragma unroll
        for (int kk = 0; kk < 16; kk += 8) {
            // B fragments for this k8-step: 4 n-tiles x 2 regs, hi+lo
            uint32_t bhi[4][2], blo[4][2];
            #pragma unroll
            for (int nj = 0; nj < 4; ++nj) {
                const int n = wn * 32 + nj * 8 + g;
                #pragma unroll
                for (int e = 0; e < 2; ++e) {
                    const float bv = bs[swidx(n, kk + cq + 4 * e)];
                    tf32_split(bv, bhi[nj][e], blo[nj][e]);
                }
            }
            // A fragments per m-tile, then 12 mma (4 nj x 3 split terms)
            #pragma unroll
            for (int mi = 0; mi < 4; ++mi) {
                const int ra = wm * 64 + mi * 16 + g;
                uint32_t ahi[4], alo[4];
                {
                    const float x0 = as[swidx(ra,     kk + cq)];
                    const float x1 = as[swidx(ra + 8, kk + cq)];
                    const float x2 = as[swidx(ra,     kk + cq + 4)];
                    const float x3 = as[swidx(ra + 8, kk + cq + 4)];
                    tf32_split(x0, ahi[0], alo[0]);
                    tf32_split(x1, ahi[1], alo[1]);
                    tf32_split(x2, ahi[2], alo[2]);
                    tf32_split(x3, ahi[3], alo[3]);
                }
                #pragma unroll
                for (int nj = 0; nj < 4; ++nj) {
                    mma_tf32(acc[mi][nj], ahi, bhi[nj]);
                    mma_tf32(acc[mi][nj], ahi, blo[nj]);
                    mma_tf32(acc[mi][nj], alo, bhi[nj]);
                }
            }
        }

        if (has_next) {
            const int nb = buf ^ 1;
            *(float4*)&As[nb][swidx(r0s, chs * 4)] = pa0;
            *(float4*)&As[nb][swidx(r1s, chs * 4)] = pa1;
            *(float4*)&Bs[nb][swidx(r0s, chs * 4)] = pb0;
            *(float4*)&Bs[nb][swidx(r1s, chs * 4)] = pb1;
            __syncthreads();
            buf = nb;
        }
    }

    // epilogue: c0/c1 at (row, 2cq), c2/c3 at (row+8, 2cq)
    #pragma unroll
    for (int mi = 0; mi < 4; ++mi) {
        const int row = bm + wm * 64 + mi * 16 + g;
        #pragma unroll
        for (int nj = 0; nj < 4; ++nj) {
            const int col = bn + wn * 32 + nj * 8 + 2 * cq;
            float2 lo = make_float2(acc[mi][nj][0], acc[mi][nj][1]);
            float2 hi = make_float2(acc[mi][nj][2], acc[mi][nj][3]);
            *(float2*)(C + (size_t)row * N + col)       = lo;
            *(float2*)(C + (size_t)(row + 8) * N + col) = hi;
        }
    }
}

// ---------------------------------------------------------------------------
// Kernel 3: RoPE + causal attention over frames (16x16 per (n,h)).
// ---------------------------------------------------------------------------
__global__ __launch_bounds__(64) void attn_kernel()
{
    const int nb = blockIdx.x;
    const int n  = nb >> 4;
    const int h  = nb & 15;
    const int tid = threadIdx.x;

    __shared__ float qs[FRAMES][HD + 1];
    __shared__ float ks[FRAMES][HD + 1];
    __shared__ float vs[FRAMES][HD + 1];
    __shared__ float P [FRAMES][FRAMES + 1];

    const float* base = g_qkv + (size_t)n * FRAMES * QKV_N;

    for (int idx = tid; idx < FRAMES * HD; idx += 64) {
        const int t = idx >> 6;
        const int d = idx & 63;
        const size_t r = (size_t)t * QKV_N + h * HD + d;
        qs[t][d] = base[r];
        ks[t][d] = base[r + HIDDEN];
        vs[t][d] = base[r + 2 * HIDDEN];
    }
    __syncthreads();

    for (int idx = tid; idx < FRAMES * 32; idx += 64) {
        const int t = idx >> 5;
        const int d = idx & 31;
        const float inv = __expf(-(float)d * 0.28782313662425576f);
        float sn, cs;
        __sincosf((float)t * inv, &sn, &cs);
        const float q1 = qs[t][d], q2 = qs[t][d + 32];
        qs[t][d]      = q1 * cs - q2 * sn;
        qs[t][d + 32] = q2 * cs + q1 * sn;
        const float k1 = ks[t][d], k2 = ks[t][d + 32];
        ks[t][d]      = k1 * cs - k2 * sn;
        ks[t][d + 32] = k2 * cs + k1 * sn;
    }
    __syncthreads();

    for (int idx = tid; idx < FRAMES * FRAMES; idx += 64) {
        const int i = idx >> 4;
        const int j = idx & 15;
        float v = -INFINITY;
        if (j <= i) {
            float acc = 0.f;
            #pragma unroll
            for (int d = 0; d < HD; ++d) acc += qs[i][d] * ks[j][d];
            v = acc * 0.125f;
        }
        P[i][j] = v;
    }
    __syncthreads();

    if (tid < FRAMES) {
        const int i = tid;
        float m = -INFINITY;
        for (int j = 0; j <= i; ++j) m = fmaxf(m, P[i][j]);
        float sum = 0.f;
        for (int j = 0; j <= i; ++j) { const float e = expf(P[i][j] - m); P[i][j] = e; sum += e; }
        const float r = 1.f / sum;
        for (int j = 0; j <= i; ++j) P[i][j] *= r;
        for (int j = i + 1; j < FRAMES; ++j) P[i][j] = 0.f;
    }
    __syncthreads();

    const int d = tid;
    const int b = n >> 10;
    const int s = n & 1023;
    #pragma unroll
    for (int i = 0; i < FRAMES; ++i) {
        float acc = 0.f;
        #pragma unroll
        for (int j = 0; j < FRAMES; ++j) acc += P[i][j] * vs[j][d];
        g_attn[(size_t)(b * 16384 + i * 1024 + s) * HIDDEN + h * HD + d] = acc;
    }
}

// ---------------------------------------------------------------------------
// Launch
// ---------------------------------------------------------------------------
extern "C" void kernel_launch(void* const* d_in, const int* in_sizes, int n_in,
                              void* d_out, int out_size)
{
    const float* x      = (const float*)d_in[0];
    const float* w_qkv  = (const float*)d_in[1];
    const float* w_out  = (const float*)d_in[2];
    const float* gamma  = (const float*)d_in[3];
    const float* beta   = (const float*)d_in[4];
    float* out = (float*)d_out;

    float *xt, *qkv, *attn;
    cudaGetSymbolAddress((void**)&xt,   g_xt);
    cudaGetSymbolAddress((void**)&qkv,  g_qkv);
    cudaGetSymbolAddress((void**)&attn, g_attn);

    // 1. LayerNorm + temporal transpose
    ln_transpose_kernel<<<TOKENS, 256>>>(x, gamma, beta);

    // 2. QKV projection: [32768,1024] x [3072,1024]^T
    {
        dim3 grid(QKV_N / 128, TOKENS / 128);
        sgemm_tf32x3<<<grid, 256>>>(xt, w_qkv, qkv, TOKENS, QKV_N, HIDDEN);
    }

    // 3. RoPE + causal attention, writes final token order
    attn_kernel<<<NSEQ * NH, 64>>>();

    // 4. Output projection: [32768,1024] x [1024,1024]^T -> d_out
    {
        dim3 grid(HIDDEN / 128, TOKENS / 128);
        sgemm_tf32x3<<<grid, 256>>>(attn, w_out, out, TOKENS, HIDDEN, HIDDEN);
    }
}

// round 5
// speedup vs baseline: 2.8036x; 2.2236x over previous
#include <cuda_runtime.h>
#include <cuda_bf16.h>
#include <cstdint>

// ---------------------------------------------------------------------------
// Problem constants
// ---------------------------------------------------------------------------
#define HIDDEN   1024
#define FRAMES   16
#define SPATIAL  1024
#define BATCH    2
#define NSEQ     (BATCH*SPATIAL)        // 2048
#define TOKENS   (BATCH*FRAMES*SPATIAL) // 32768
#define NH       16
#define HD       64
#define QKV_N    3072
#define K3       3072                   // split K' = 3*1024

// ---------------------------------------------------------------------------
// Scratch
// ---------------------------------------------------------------------------
__device__ __nv_bfloat16 g_xts[(size_t)TOKENS * K3];  // LN'd+transposed [hi|lo|hi]
__device__ __nv_bfloat16 g_wqs[(size_t)QKV_N  * K3];  // w_qkv split [hi|hi|lo]
__device__ __nv_bfloat16 g_wos[(size_t)HIDDEN * K3];  // w_out split [hi|hi|lo]
__device__ float         g_qkv[(size_t)TOKENS * QKV_N];
__device__ __nv_bfloat16 g_ats[(size_t)TOKENS * K3];  // attn out split [hi|lo|hi]

// ---------------------------------------------------------------------------
// PTX helpers (all sm_80-era: compile at base sm_103 target)
// ---------------------------------------------------------------------------
__device__ __forceinline__ uint32_t smem_u32(const void* p) {
    uint32_t a;
    asm("{ .reg .u64 t; cvta.to.shared.u64 t, %1; cvt.u32.u64 %0, t; }" : "=r"(a) : "l"(p));
    return a;
}
__device__ __forceinline__ void cp16(uint32_t dst, const void* src) {
    asm volatile("cp.async.cg.shared.global [%0], [%1], 16;" :: "r"(dst), "l"(src));
}
#define CP_COMMIT() asm volatile("cp.async.commit_group;" ::: "memory")
#define CP_WAIT1()  asm volatile("cp.async.wait_group 1;" ::: "memory")

__device__ __forceinline__ void ldmx4(uint32_t addr, uint32_t* r) {
    asm volatile("ldmatrix.sync.aligned.m8n8.x4.shared.b16 {%0,%1,%2,%3}, [%4];"
        : "=r"(r[0]), "=r"(r[1]), "=r"(r[2]), "=r"(r[3]) : "r"(addr));
}
__device__ __forceinline__ void mma_bf16(float* d, const uint32_t* a, const uint32_t* b) {
    asm volatile("mma.sync.aligned.m16n8k16.row.col.f32.bf16.bf16.f32 "
        "{%0,%1,%2,%3},{%4,%5,%6,%7},{%8,%9},{%0,%1,%2,%3};"
        : "+f"(d[0]), "+f"(d[1]), "+f"(d[2]), "+f"(d[3])
        : "r"(a[0]), "r"(a[1]), "r"(a[2]), "r"(a[3]), "r"(b[0]), "r"(b[1]));
}

// byte offset of element-chunk (r, ch) inside a [rows x 32bf16] tile (64B rows,
// four 16B chunks), XOR-swizzled: conflict-free for cp.async stores and ldmatrix
__device__ __forceinline__ uint32_t toff(int r, int ch) {
    return (uint32_t)(r * 64 + ((ch ^ ((r >> 1) & 3)) << 4));
}

// ---------------------------------------------------------------------------
// bf16 split helper:  x = hi + lo
// ---------------------------------------------------------------------------
__device__ __forceinline__ void bsplit(float x, __nv_bfloat16& h, __nv_bfloat16& l) {
    h = __float2bfloat16_rn(x);
    l = __float2bfloat16_rn(x - __bfloat162float(h));
}

// ---------------------------------------------------------------------------
// Kernel 1: LayerNorm + temporal transpose -> split bf16 [hi | lo | hi]
// ---------------------------------------------------------------------------
__global__ __launch_bounds__(256) void ln_transpose_kernel(
    const float* __restrict__ x,
    const float* __restrict__ gamma,
    const float* __restrict__ beta)
{
    const int token = blockIdx.x;
    const int b  = token >> 14;
    const int sg = token & 16383;
    const int t  = sg >> 10;
    const int s  = sg & 1023;

    const int tid = threadIdx.x;
    const float4 v = ((const float4*)(x + (size_t)token * HIDDEN))[tid];

    float sum = v.x + v.y + v.z + v.w;
    float sq  = v.x*v.x + v.y*v.y + v.z*v.z + v.w*v.w;

    #pragma unroll
    for (int o = 16; o > 0; o >>= 1) {
        sum += __shfl_xor_sync(0xffffffffu, sum, o);
        sq  += __shfl_xor_sync(0xffffffffu, sq,  o);
    }
    __shared__ float s_sum[8], s_sq[8];
    __shared__ float s_mu, s_rstd;
    if ((tid & 31) == 0) { s_sum[tid >> 5] = sum; s_sq[tid >> 5] = sq; }
    __syncthreads();
    if (tid == 0) {
        float ts = 0.f, tq = 0.f;
        #pragma unroll
        for (int i = 0; i < 8; ++i) { ts += s_sum[i]; tq += s_sq[i]; }
        const float mu  = ts * (1.0f / HIDDEN);
        const float var = tq * (1.0f / HIDDEN) - mu * mu;
        s_mu = mu;
        s_rstd = rsqrtf(var + 1e-5f);
    }
    __syncthreads();
    const float mu = s_mu, rs = s_rstd;

    const float4 g  = ((const float4*)gamma)[tid];
    const float4 be = ((const float4*)beta)[tid];
    float o[4];
    o[0] = (v.x - mu) * rs * g.x + be.x;
    o[1] = (v.y - mu) * rs * g.y + be.y;
    o[2] = (v.z - mu) * rs * g.z + be.z;
    o[3] = (v.w - mu) * rs * g.w + be.w;

    __nv_bfloat16 h[4], l[4];
    #pragma unroll
    for (int i = 0; i < 4; ++i) bsplit(o[i], h[i], l[i]);

    const size_t orow = (size_t)(b * SPATIAL + s) * FRAMES + t;
    __nv_bfloat16* dst = g_xts + orow * K3 + 4 * tid;
    *(uint2*)(dst)        = *(uint2*)h;
    *(uint2*)(dst + 1024) = *(uint2*)l;
    *(uint2*)(dst + 2048) = *(uint2*)h;
}

// ---------------------------------------------------------------------------
// weights fp32 [rows,1024] -> bf16 [rows,3072] as [hi | hi | lo]
// ---------------------------------------------------------------------------
__global__ __launch_bounds__(256) void wsplit_kernel(
    const float* __restrict__ w, __nv_bfloat16* __restrict__ ws, int total)
{
    const int idx = blockIdx.x * 256 + threadIdx.x;
    if (idx >= total) return;
    const int r = idx >> 10;
    const int c = idx & 1023;
    __nv_bfloat16 h, l;
    bsplit(w[idx], h, l);
    __nv_bfloat16* dst = ws + (size_t)r * K3 + c;
    dst[0]    = h;
    dst[1024] = h;
    dst[2048] = l;
}

// ---------------------------------------------------------------------------
// bf16 mma.sync GEMM: C[M,N] = A[M,K3] * B[N,K3]^T  (bf16 in, fp32 out)
// BM=128, BN=256, BK=32; 512 threads (16 warps 2x8, warp tile 64x32);
// cp.async double-buffered; ldmatrix fragments; m16n8k16 bf16 HMMA.
// ---------------------------------------------------------------------------
#define GBM 128
#define GBN 256
#define GBK 32
#define KCH (K3/GBK)     // 96
#define A_STAGE (GBM*GBK*2)   // 8192 B
#define B_STAGE (GBN*GBK*2)   // 16384 B

__global__ __launch_bounds__(512, 1) void gemm_bf16_mma(
    const __nv_bfloat16* __restrict__ A,
    const __nv_bfloat16* __restrict__ B,
    float* __restrict__ C, int N)
{
    __shared__ __nv_bfloat16 As[2][GBM * GBK];
    __shared__ __nv_bfloat16 Bs[2][GBN * GBK];

    const int tid  = threadIdx.x;
    const int lane = tid & 31;
    const int wid  = tid >> 5;
    const int wm   = wid >> 3;         // 0..1
    const int wn   = wid & 7;          // 0..7
    const int bm   = blockIdx.y * GBM;
    const int bn   = blockIdx.x * GBN;

    const uint32_t aBase = smem_u32(&As[0][0]);
    const uint32_t bBase = smem_u32(&Bs[0][0]);

    // staging: A 512 chunks (1/thread), B 1024 chunks (2/thread)
    const int sr = tid >> 2;           // 0..127
    const int sc = tid & 3;
    const char* aSrc  = (const char*)(A + (size_t)(bm + sr) * K3) + sc * 16;
    const char* bSrc0 = (const char*)(B + (size_t)(bn + sr) * K3) + sc * 16;
    const char* bSrc1 = (const char*)(B + (size_t)(bn + sr + 128) * K3) + sc * 16;
    const uint32_t aDst  = toff(sr, sc);
    const uint32_t bDst0 = toff(sr, sc);
    const uint32_t bDst1 = toff(sr + 128, sc);

    #define LOAD_STAGE(c, s)                                         \
    {                                                                \
        const int koff = (c) * 64;                                   \
        cp16(aBase + (s) * A_STAGE + aDst,  aSrc  + koff);           \
        cp16(bBase + (s) * B_STAGE + bDst0, bSrc0 + koff);           \
        cp16(bBase + (s) * B_STAGE + bDst1, bSrc1 + koff);           \
    }

    // fragment smem offsets (within one stage), precomputed
    uint32_t a_off[4][2], b_off[2][2];
    #pragma unroll
    for (int mi = 0; mi < 4; ++mi)
        #pragma unroll
        for (int kk = 0; kk < 2; ++kk) {
            const int r  = wm * 64 + mi * 16 + (lane & 7) + ((lane >> 3) & 1) * 8;
            const int ch = kk * 2 + (lane >> 4);
            a_off[mi][kk] = toff(r, ch);
        }
    #pragma unroll
    for (int p = 0; p < 2; ++p)
        #pragma unroll
        for (int kk = 0; kk < 2; ++kk) {
            const int r  = wn * 32 + p * 16 + (lane & 7) + (lane >> 4) * 8;
            const int ch = kk * 2 + ((lane >> 3) & 1);
            b_off[p][kk] = toff(r, ch);
        }

    float acc[4][4][4];
    #pragma unroll
    for (int i = 0; i < 4; ++i)
        #pragma unroll
        for (int j = 0; j < 4; ++j)
            #pragma unroll
            for (int e = 0; e < 4; ++e) acc[i][j][e] = 0.f;

    // prologue: stages 0,1
    LOAD_STAGE(0, 0); CP_COMMIT();
    LOAD_STAGE(1, 1); CP_COMMIT();

    #pragma unroll 1
    for (int c = 0; c < KCH; ++c) {
        CP_WAIT1();
        __syncthreads();

        const int s = c & 1;
        const uint32_t ab = aBase + s * A_STAGE;
        const uint32_t bb = bBase + s * B_STAGE;

        #pragma unroll
        for (int kk = 0; kk < 2; ++kk) {
            uint32_t bq[2][4];
            ldmx4(bb + b_off[0][kk], bq[0]);
            ldmx4(bb + b_off[1][kk], bq[1]);
            #pragma unroll
            for (int mi = 0; mi < 4; ++mi) {
                uint32_t aq[4];
                ldmx4(ab + a_off[mi][kk], aq);
                #pragma unroll
                for (int nj = 0; nj < 4; ++nj)
                    mma_bf16(acc[mi][nj], aq, &bq[nj >> 1][(nj & 1) * 2]);
            }
        }

        __syncthreads();
        if (c + 2 < KCH) LOAD_STAGE(c + 2, s);
        CP_COMMIT();
    }
    #undef LOAD_STAGE

    // epilogue
    #pragma unroll
    for (int mi = 0; mi < 4; ++mi) {
        const int row = bm + wm * 64 + mi * 16 + (lane >> 2);
        #pragma unroll
        for (int nj = 0; nj < 4; ++nj) {
            const int col = bn + wn * 32 + nj * 8 + (lane & 3) * 2;
            *(float2*)(C + (size_t)row * N + col)       = make_float2(acc[mi][nj][0], acc[mi][nj][1]);
            *(float2*)(C + (size_t)(row + 8) * N + col) = make_float2(acc[mi][nj][2], acc[mi][nj][3]);
        }
    }
}

// ---------------------------------------------------------------------------
// Kernel 3: RoPE + causal attention; writes split bf16 [hi|lo|hi] final order
// ---------------------------------------------------------------------------
__global__ __launch_bounds__(64) void attn_kernel()
{
    const int nb = blockIdx.x;
    const int n  = nb >> 4;
    const int hh = nb & 15;
    const int tid = threadIdx.x;

    __shared__ float qs[FRAMES][HD + 1];
    __shared__ float ks[FRAMES][HD + 1];
    __shared__ float vs[FRAMES][HD + 1];
    __shared__ float P [FRAMES][FRAMES + 1];

    const float* bptr = g_qkv + (size_t)n * FRAMES * QKV_N;

    for (int idx = tid; idx < FRAMES * HD; idx += 64) {
        const int t = idx >> 6;
        const int d = idx & 63;
        const size_t r = (size_t)t * QKV_N + hh * HD + d;
        qs[t][d] = bptr[r];
        ks[t][d] = bptr[r + HIDDEN];
        vs[t][d] = bptr[r + 2 * HIDDEN];
    }
    __syncthreads();

    for (int idx = tid; idx < FRAMES * 32; idx += 64) {
        const int t = idx >> 5;
        const int d = idx & 31;
        const float inv = __expf(-(float)d * 0.28782313662425576f);
        float sn, cs;
        __sincosf((float)t * inv, &sn, &cs);
        const float q1 = qs[t][d], q2 = qs[t][d + 32];
        qs[t][d]      = q1 * cs - q2 * sn;
        qs[t][d + 32] = q2 * cs + q1 * sn;
        const float k1 = ks[t][d], k2 = ks[t][d + 32];
        ks[t][d]      = k1 * cs - k2 * sn;
        ks[t][d + 32] = k2 * cs + k1 * sn;
    }
    __syncthreads();

    for (int idx = tid; idx < FRAMES * FRAMES; idx += 64) {
        const int i = idx >> 4;
        const int j = idx & 15;
        float v = -INFINITY;
        if (j <= i) {
            float acc = 0.f;
            #pragma unroll
            for (int d = 0; d < HD; ++d) acc += qs[i][d] * ks[j][d];
            v = acc * 0.125f;
        }
        P[i][j] = v;
    }
    __syncthreads();

    if (tid < FRAMES) {
        const int i = tid;
        float m = -INFINITY;
        for (int j = 0; j <= i; ++j) m = fmaxf(m, P[i][j]);
        float sum = 0.f;
        for (int j = 0; j <= i; ++j) { const float e = expf(P[i][j] - m); P[i][j] = e; sum += e; }
        const float r = 1.f / sum;
        for (int j = 0; j <= i; ++j) P[i][j] *= r;
        for (int j = i + 1; j < FRAMES; ++j) P[i][j] = 0.f;
    }
    __syncthreads();

    const int d = tid;
    const int b = n >> 10;
    const int s = n & 1023;
    #pragma unroll
    for (int i = 0; i < FRAMES; ++i) {
        float acc = 0.f;
        #pragma unroll
        for (int j = 0; j < FRAMES; ++j) acc += P[i][j] * vs[j][d];
        __nv_bfloat16 h, l;
        bsplit(acc, h, l);
        __nv_bfloat16* dst = g_ats + (size_t)(b * 16384 + i * 1024 + s) * K3 + hh * HD + d;
        dst[0]    = h;
        dst[1024] = l;
        dst[2048] = h;
    }
}

// ---------------------------------------------------------------------------
// Launch
// ---------------------------------------------------------------------------
extern "C" void kernel_launch(void* const* d_in, const int* in_sizes, int n_in,
                              void* d_out, int out_size)
{
    const float* x      = (const float*)d_in[0];
    const float* w_qkv  = (const float*)d_in[1];
    const float* w_out  = (const float*)d_in[2];
    const float* gamma  = (const float*)d_in[3];
    const float* beta   = (const float*)d_in[4];
    float* out = (float*)d_out;

    __nv_bfloat16 *xts, *wqs, *wos, *ats;
    float *qkv;
    cudaGetSymbolAddress((void**)&xts, g_xts);
    cudaGetSymbolAddress((void**)&wqs, g_wqs);
    cudaGetSymbolAddress((void**)&wos, g_wos);
    cudaGetSymbolAddress((void**)&qkv, g_qkv);
    cudaGetSymbolAddress((void**)&ats, g_ats);

    // 1. LN + temporal transpose -> split bf16
    ln_transpose_kernel<<<TOKENS, 256>>>(x, gamma, beta);

    // 1b. weight splits
    wsplit_kernel<<<(QKV_N * 1024 + 255) / 256, 256>>>(w_qkv, wqs, QKV_N * 1024);
    wsplit_kernel<<<(HIDDEN * 1024 + 255) / 256, 256>>>(w_out, wos, HIDDEN * 1024);

    // 2. QKV projection: [32768,3072] x [3072,3072]^T -> fp32
    {
        dim3 grid(QKV_N / GBN, TOKENS / GBM);
        gemm_bf16_mma<<<grid, 512>>>(xts, wqs, qkv, QKV_N);
    }

    // 3. RoPE + causal attention -> split bf16 in final token order
    attn_kernel<<<NSEQ * NH, 64>>>();

    // 4. Output projection -> d_out fp32
    {
        dim3 grid(HIDDEN / GBN, TOKENS / GBM);
        gemm_bf16_mma<<<grid, 512>>>(ats, wos, out, HIDDEN);
    }
}